// round 3
// baseline (speedup 1.0000x reference)
#include <cuda_runtime.h>
#include <math.h>

// Problem constants (fixed shapes from reference)
#define DMODEL 1024
#define NHEADS 16
#define DK     64
#define BATCH  2
#define SEQ    2048
#define MROWS  (BATCH*SEQ)   // 4096

// Scratch (device globals; no allocation allowed)
__device__ float g_Qh[BATCH*NHEADS*SEQ*DK];   // [B][H][S][dk], Q pre-scaled by 1/sqrt(dk)
__device__ float g_Kh[BATCH*NHEADS*SEQ*DK];
__device__ float g_Vh[BATCH*NHEADS*SEQ*DK];
__device__ float g_ctx[BATCH*SEQ*DMODEL];     // [B][S][H*dk]

// ---------------------------------------------------------------------------
// GEMM: C = (A[M,K] @ W[K,N] + bias) * scale
// M=4096, N=1024, K=1024. BM=BN=128, BK=16, 256 threads, 8x8 per thread.
// HEAD_MODE=1: store into [B][H][S][dk] layout. HEAD_MODE=0: plain row-major.
// ---------------------------------------------------------------------------
template <int HEAD_MODE>
__global__ __launch_bounds__(256)
void gemm_bias_kernel(const float* __restrict__ A,
                      const float* __restrict__ W,
                      const float* __restrict__ bias,
                      float* __restrict__ C,
                      float scale)
{
    constexpr int N = DMODEL, K = DMODEL;
    constexpr int BM = 128, BN = 128, BK = 16;

    __shared__ float As[BK][BM];   // transposed A tile: As[k][m]
    __shared__ float Ws[BK][BN];   // Ws[k][n]

    const int tid = threadIdx.x;
    const int tx  = tid & 15;      // 0..15
    const int ty  = tid >> 4;      // 0..15
    const int mbase = blockIdx.y * BM;
    const int nbase = blockIdx.x * BN;

    // A-load mapping: 128 rows x 4 float4 (k) = 512 float4; 2 per thread
    const int a_row = tid >> 2;    // 0..63
    const int a_c4  = tid & 3;     // 0..3
    // W-load mapping: 16 k-rows x 32 float4 (n) = 512 float4; 2 per thread
    const int w_k  = tid >> 5;     // 0..7
    const int w_n4 = tid & 31;     // 0..31

    float acc[8][8];
#pragma unroll
    for (int i = 0; i < 8; ++i)
#pragma unroll
        for (int j = 0; j < 8; ++j) acc[i][j] = 0.0f;

    for (int k0 = 0; k0 < K; k0 += BK) {
        __syncthreads();
#pragma unroll
        for (int r = 0; r < 2; ++r) {
            int row = a_row + 64 * r;
            float4 v = *(const float4*)&A[(size_t)(mbase + row) * K + k0 + a_c4 * 4];
            As[a_c4 * 4 + 0][row] = v.x;
            As[a_c4 * 4 + 1][row] = v.y;
            As[a_c4 * 4 + 2][row] = v.z;
            As[a_c4 * 4 + 3][row] = v.w;
        }
#pragma unroll
        for (int r = 0; r < 2; ++r) {
            int kk = w_k + 8 * r;
            float4 v = *(const float4*)&W[(size_t)(k0 + kk) * N + nbase + w_n4 * 4];
            *(float4*)&Ws[kk][w_n4 * 4] = v;
        }
        __syncthreads();

#pragma unroll
        for (int kk = 0; kk < BK; ++kk) {
            float a[8], w[8];
            *(float4*)&a[0] = *(const float4*)&As[kk][ty * 8];
            *(float4*)&a[4] = *(const float4*)&As[kk][ty * 8 + 4];
            *(float4*)&w[0] = *(const float4*)&Ws[kk][tx * 8];
            *(float4*)&w[4] = *(const float4*)&Ws[kk][tx * 8 + 4];
#pragma unroll
            for (int i = 0; i < 8; ++i)
#pragma unroll
                for (int j = 0; j < 8; ++j)
                    acc[i][j] += a[i] * w[j];
        }
    }

    // Epilogue
    const int ncol0 = nbase + tx * 8;
    float bv[8];
#pragma unroll
    for (int j = 0; j < 8; ++j) bv[j] = bias[ncol0 + j];

#pragma unroll
    for (int i = 0; i < 8; ++i) {
        int m = mbase + ty * 8 + i;
        float out[8];
#pragma unroll
        for (int j = 0; j < 8; ++j) out[j] = (acc[i][j] + bv[j]) * scale;

        if (HEAD_MODE) {
            // n = h*64 + d ; tx*8..tx*8+7 lies within one head (8 | 64)
            int b = m >> 11;           // /2048
            int s = m & 2047;
            int h = ncol0 >> 6;
            int d = ncol0 & 63;
            float* dst = &C[(((size_t)(b * NHEADS + h)) * SEQ + s) * DK + d];
            *(float4*)&dst[0] = make_float4(out[0], out[1], out[2], out[3]);
            *(float4*)&dst[4] = make_float4(out[4], out[5], out[6], out[7]);
        } else {
            float* dst = &C[(size_t)m * N + ncol0];
            *(float4*)&dst[0] = make_float4(out[0], out[1], out[2], out[3]);
            *(float4*)&dst[4] = make_float4(out[4], out[5], out[6], out[7]);
        }
    }
}

// ---------------------------------------------------------------------------
// Flash attention: per (b, h, q-tile of 64). 256 threads, 4x4 per thread.
// Q pre-scaled by 1/sqrt(dk). Online softmax, fp32.
// Smem: Qs[64][68], Kt[64][68] (K transposed: Kt[d][key]), Vs[64][68], Ps[64][68]
// ---------------------------------------------------------------------------
#define AST 68  // padded stride (multiple of 4 for float4, 68%32==4 for banks)
#define ATTN_SMEM (4 * 64 * AST * 4)

__global__ __launch_bounds__(256)
void attn_kernel(const float* __restrict__ Qh,
                 const float* __restrict__ Kh,
                 const float* __restrict__ Vh,
                 float* __restrict__ ctx)
{
    extern __shared__ float sm[];
    float* Qs = sm;
    float* Kt = sm + 64 * AST;
    float* Vs = sm + 2 * 64 * AST;
    float* Ps = sm + 3 * 64 * AST;

    const int tid = threadIdx.x;
    const int tx  = tid & 15;   // 0..15 : dk/key cols (4 each)
    const int ty  = tid >> 4;   // 0..15 : q rows (4 each)
    const int qt = blockIdx.x;
    const int h  = blockIdx.y;
    const int b  = blockIdx.z;

    const float* Qbase = Qh + (((size_t)(b * NHEADS + h)) * SEQ + qt * 64) * DK;
    const float* Kbase = Kh + ((size_t)(b * NHEADS + h)) * SEQ * DK;
    const float* Vbase = Vh + ((size_t)(b * NHEADS + h)) * SEQ * DK;

    // Load Q tile: 64x64 floats = 1024 float4, 4 per thread
#pragma unroll
    for (int it = 0; it < 4; ++it) {
        int idx = tid + it * 256;
        int row = idx >> 4;
        int d4  = idx & 15;
        float4 v = *(const float4*)&Qbase[row * DK + d4 * 4];
        *(float4*)&Qs[row * AST + d4 * 4] = v;
    }

    float m_i[4], l_i[4], o[4][4];
#pragma unroll
    for (int i = 0; i < 4; ++i) {
        m_i[i] = -INFINITY;
        l_i[i] = 0.0f;
#pragma unroll
        for (int j = 0; j < 4; ++j) o[i][j] = 0.0f;
    }

    const int r0 = ty * 4;   // first q row of this thread
    const int c0 = tx * 4;   // first key/dk col of this thread

    for (int kb = 0; kb < SEQ / 64; ++kb) {
        __syncthreads();   // protect K/V/P from previous iteration's readers
        // Load K (transposed into Kt[d][key]) and V (Vs[key][d])
#pragma unroll
        for (int it = 0; it < 4; ++it) {
            int idx = tid + it * 256;
            int r  = idx >> 4;
            int d4 = idx & 15;
            float4 kv = *(const float4*)&Kbase[(size_t)(kb * 64 + r) * DK + d4 * 4];
            Kt[(d4 * 4 + 0) * AST + r] = kv.x;
            Kt[(d4 * 4 + 1) * AST + r] = kv.y;
            Kt[(d4 * 4 + 2) * AST + r] = kv.z;
            Kt[(d4 * 4 + 3) * AST + r] = kv.w;
            float4 vv = *(const float4*)&Vbase[(size_t)(kb * 64 + r) * DK + d4 * 4];
            *(float4*)&Vs[r * AST + d4 * 4] = vv;
        }
        __syncthreads();

        // S = Q @ K^T  (Q pre-scaled)
        float s[4][4];
#pragma unroll
        for (int i = 0; i < 4; ++i)
#pragma unroll
            for (int j = 0; j < 4; ++j) s[i][j] = 0.0f;

#pragma unroll
        for (int d4 = 0; d4 < 16; ++d4) {
            float a[4][4];
#pragma unroll
            for (int i = 0; i < 4; ++i) {
                float4 q = *(const float4*)&Qs[(r0 + i) * AST + d4 * 4];
                a[i][0] = q.x; a[i][1] = q.y; a[i][2] = q.z; a[i][3] = q.w;
            }
#pragma unroll
            for (int t = 0; t < 4; ++t) {
                float4 kv = *(const float4*)&Kt[(d4 * 4 + t) * AST + c0];
#pragma unroll
                for (int i = 0; i < 4; ++i) {
                    s[i][0] += a[i][t] * kv.x;
                    s[i][1] += a[i][t] * kv.y;
                    s[i][2] += a[i][t] * kv.z;
                    s[i][3] += a[i][t] * kv.w;
                }
            }
        }

        // Online softmax per row (row group = 16 lanes with same ty)
#pragma unroll
        for (int i = 0; i < 4; ++i) {
            float mx = fmaxf(fmaxf(s[i][0], s[i][1]), fmaxf(s[i][2], s[i][3]));
#pragma unroll
            for (int off = 8; off >= 1; off >>= 1)
                mx = fmaxf(mx, __shfl_xor_sync(0xffffffffu, mx, off, 16));
            float m_new = fmaxf(m_i[i], mx);
            float fac = expf(m_i[i] - m_new);
            float p0 = expf(s[i][0] - m_new);
            float p1 = expf(s[i][1] - m_new);
            float p2 = expf(s[i][2] - m_new);
            float p3 = expf(s[i][3] - m_new);
            float rs = (p0 + p1) + (p2 + p3);
#pragma unroll
            for (int off = 8; off >= 1; off >>= 1)
                rs += __shfl_xor_sync(0xffffffffu, rs, off, 16);
            l_i[i] = l_i[i] * fac + rs;
            m_i[i] = m_new;
#pragma unroll
            for (int j = 0; j < 4; ++j) o[i][j] *= fac;
            *(float4*)&Ps[(r0 + i) * AST + c0] = make_float4(p0, p1, p2, p3);
        }
        __syncthreads();   // Ps visible to all threads

        // O += P @ V
#pragma unroll
        for (int k4 = 0; k4 < 16; ++k4) {
            float p[4][4];
#pragma unroll
            for (int i = 0; i < 4; ++i) {
                float4 pv = *(const float4*)&Ps[(r0 + i) * AST + k4 * 4];
                p[i][0] = pv.x; p[i][1] = pv.y; p[i][2] = pv.z; p[i][3] = pv.w;
            }
#pragma unroll
            for (int t = 0; t < 4; ++t) {
                float4 vv = *(const float4*)&Vs[(k4 * 4 + t) * AST + c0];
#pragma unroll
                for (int i = 0; i < 4; ++i) {
                    o[i][0] += p[i][t] * vv.x;
                    o[i][1] += p[i][t] * vv.y;
                    o[i][2] += p[i][t] * vv.z;
                    o[i][3] += p[i][t] * vv.w;
                }
            }
        }
    }

    // Write ctx[(b, s, h*64+d)]
#pragma unroll
    for (int i = 0; i < 4; ++i) {
        float inv = 1.0f / l_i[i];
        int srow = qt * 64 + r0 + i;
        float* dst = &ctx[((size_t)(b * SEQ + srow)) * DMODEL + h * 64 + c0];
        *(float4*)dst = make_float4(o[i][0] * inv, o[i][1] * inv,
                                    o[i][2] * inv, o[i][3] * inv);
    }
}

// ---------------------------------------------------------------------------
// Launch
// ---------------------------------------------------------------------------
extern "C" void kernel_launch(void* const* d_in, const int* in_sizes, int n_in,
                              void* d_out, int out_size)
{
    const float* q  = (const float*)d_in[0];
    const float* k  = (const float*)d_in[1];
    const float* v  = (const float*)d_in[2];
    const float* Wq = (const float*)d_in[3];
    const float* bq = (const float*)d_in[4];
    const float* Wk = (const float*)d_in[5];
    const float* bk = (const float*)d_in[6];
    const float* Wv = (const float*)d_in[7];
    const float* bv = (const float*)d_in[8];
    const float* Wo = (const float*)d_in[9];
    const float* bo = (const float*)d_in[10];
    float* out = (float*)d_out;

    float *pQh, *pKh, *pVh, *pCtx;
    cudaGetSymbolAddress((void**)&pQh, g_Qh);
    cudaGetSymbolAddress((void**)&pKh, g_Kh);
    cudaGetSymbolAddress((void**)&pVh, g_Vh);
    cudaGetSymbolAddress((void**)&pCtx, g_ctx);

    cudaFuncSetAttribute(attn_kernel, cudaFuncAttributeMaxDynamicSharedMemorySize,
                         ATTN_SMEM);

    dim3 ggrid(DMODEL / 128, MROWS / 128);   // (8, 32)
    const float qscale = 0.125f;             // 1/sqrt(64)

    gemm_bias_kernel<1><<<ggrid, 256>>>(q, Wq, bq, pQh, qscale);
    gemm_bias_kernel<1><<<ggrid, 256>>>(k, Wk, bk, pKh, 1.0f);
    gemm_bias_kernel<1><<<ggrid, 256>>>(v, Wv, bv, pVh, 1.0f);

    dim3 agrid(SEQ / 64, NHEADS, BATCH);     // (32, 16, 2)
    attn_kernel<<<agrid, 256, ATTN_SMEM>>>(pQh, pKh, pVh, pCtx);

    gemm_bias_kernel<0><<<ggrid, 256>>>(pCtx, Wo, bo, out, 1.0f);
}